// round 2
// baseline (speedup 1.0000x reference)
#include <cuda_runtime.h>
#include <math.h>

// ---------------------------------------------------------------------------
// EdgeClassNet fused implementation (Round 0: fp32 FFMA baseline)
//
//   h_node = leaky(x @ Wx + bx)                       [65536,128]  (kernel 1)
//   ef     = concat(h[row], h[col], edge_attr)        [E,272]      (fused)
//   h      = leaky(ef @ W0 + b0); 8x leaky(h@Wm+bm)   [E,256]      (fused)
//   out    = log_softmax(h @ Wlast + blast)           [E,3]        (fused)
//
// Kernel 2 keeps the per-64-edge activation tile resident in SMEM across all
// 9 layers (ping-pong buffers), so only weights stream from L2.
// ---------------------------------------------------------------------------

#define N_NODES 65536
#define E_EDGES 262144
#define D_NODE  256
#define D_HN    128       // node-MLP output dim
#define D_EDGE  272       // 128 + 128 + 16
#define HID     256
#define NEG     0.01f

// scratch: node features after node MLP (32 MB, fits easily in L2 once warm)
__device__ float g_h[(size_t)N_NODES * D_HN];
__device__ int   g_idx64;   // 1 if edge_index is int64, 0 if int32

// ---------------------------------------------------------------------------
// Detect int32 vs int64 edge_index layout at runtime (device-side, capturable).
// int64 little-endian with values in [0,65536) => every odd 32-bit word is 0.
// ---------------------------------------------------------------------------
__global__ void detect_idx_kernel(const int* __restrict__ ei32) {
    int all0 = 1;
    #pragma unroll 1
    for (int i = 0; i < 64; ++i) {
        if (ei32[2 * i + 1] != 0) { all0 = 0; break; }
    }
    g_idx64 = all0;
}

// ---------------------------------------------------------------------------
// Kernel 1: node MLP.  h_node = leaky(x @ Wx + bx),  M=65536 K=256 N=128.
// CTA: 64 rows x 128 cols, 256 threads, 8x4 register microtile per thread.
// ---------------------------------------------------------------------------
__global__ __launch_bounds__(256, 1) void node_mlp_kernel(
    const float* __restrict__ x, const float* __restrict__ Wx,
    const float* __restrict__ bx)
{
    __shared__ float Xs[16][65];    // [k][m], padded
    __shared__ float Ws[16][128];   // [k][n]

    const int tid  = threadIdx.x;
    const int row0 = blockIdx.x * 64;
    const int trow = tid >> 5;      // 0..7  (warp id)
    const int tcol = tid & 31;      // lane

    float c[8][4];
    #pragma unroll
    for (int i = 0; i < 8; ++i)
        #pragma unroll
        for (int j = 0; j < 4; ++j) c[i][j] = 0.f;

    const int lm = tid >> 2;          // 0..63 : row within tile
    const int lk = (tid & 3) * 4;     // 0,4,8,12 : k offset

    for (int kt = 0; kt < D_NODE; kt += 16) {
        // load X tile (transposed into Xs[k][m])
        float4 xv = *(const float4*)(x + (size_t)(row0 + lm) * D_NODE + kt + lk);
        Xs[lk + 0][lm] = xv.x;
        Xs[lk + 1][lm] = xv.y;
        Xs[lk + 2][lm] = xv.z;
        Xs[lk + 3][lm] = xv.w;
        // load W tile [16][128] = 512 float4, 2 per thread
        #pragma unroll
        for (int r = 0; r < 2; ++r) {
            int p  = tid + r * 256;     // float4 index
            int k  = p >> 5;            // 32 float4 per row
            int n4 = p & 31;
            *(float4*)&Ws[k][n4 * 4] =
                *(const float4*)(Wx + (size_t)(kt + k) * D_HN + n4 * 4);
        }
        __syncthreads();
        #pragma unroll
        for (int k = 0; k < 16; ++k) {
            float a[8], b[4];
            #pragma unroll
            for (int i = 0; i < 8; ++i) a[i] = Xs[k][trow * 8 + i];
            #pragma unroll
            for (int j = 0; j < 4; ++j) b[j] = Ws[k][tcol + 32 * j];
            #pragma unroll
            for (int i = 0; i < 8; ++i)
                #pragma unroll
                for (int j = 0; j < 4; ++j) c[i][j] += a[i] * b[j];
        }
        __syncthreads();
    }

    #pragma unroll
    for (int j = 0; j < 4; ++j) {
        float bb = bx[tcol + 32 * j];
        #pragma unroll
        for (int i = 0; i < 8; ++i) {
            float v = c[i][j] + bb;
            v = (v >= 0.f) ? v : NEG * v;
            g_h[(size_t)(row0 + trow * 8 + i) * D_HN + tcol + 32 * j] = v;
        }
    }
}

// ---------------------------------------------------------------------------
// Kernel 2: fused edge pipeline. One CTA = 64 edges, activations resident in
// SMEM across all layers. 256 threads, 8x8 register microtile per thread.
//
// Dynamic SMEM layout (floats):
//   Abuf [272][65]   at 0        (17680)
//   Cbuf [256][65]   at 17680    (16640)
//   Ws   [16][256]   at 34320    ( 4096)   (also reused for Wlast: 768 floats)
//   Lg   [64][4]     at 38416    (  256)
// total 38672 floats = 154688 bytes
// ---------------------------------------------------------------------------
#define SMEM_FLOATS 38672
#define SMEM_BYTES  (SMEM_FLOATS * 4)

__global__ __launch_bounds__(256, 1) void edge_mlp_kernel(
    const void*  __restrict__ edge_index,
    const float* __restrict__ edge_attr,
    const float* __restrict__ W0,    const float* __restrict__ b0,
    const float* __restrict__ Wmid,  const float* __restrict__ bmid,
    const float* __restrict__ Wlast, const float* __restrict__ blast,
    float* __restrict__ out)
{
    extern __shared__ float smf[];
    float* Abuf = smf;                    // pitch 65, 272 rows
    float* Cbuf = smf + 272 * 65;         // pitch 65, 256 rows
    float* Ws   = Cbuf + 256 * 65;        // [16][256]
    float* Lg   = Ws + 16 * 256;          // [64][4]

    const int tid  = threadIdx.x;
    const int wid  = tid >> 5;
    const int lane = tid & 31;
    const int e0   = blockIdx.x * 64;

    const bool is64 = (g_idx64 != 0);
    const int*       ei32 = (const int*)edge_index;
    const long long* ei64 = (const long long*)edge_index;

    // ---- gather: ef[k][m] = concat(h[row], h[col], edge_attr) -------------
    // warp w handles local edges w*8 .. w*8+7
    for (int el = wid * 8; el < wid * 8 + 8; ++el) {
        const int e = e0 + el;
        const int r  = is64 ? (int)ei64[e]           : ei32[e];
        const int cc = is64 ? (int)ei64[E_EDGES + e] : ei32[E_EDGES + e];
        const float* hr = g_h + (size_t)r  * D_HN;
        const float* hc = g_h + (size_t)cc * D_HN;
        #pragma unroll
        for (int u = 0; u < 4; ++u) {
            Abuf[(lane + 32 * u) * 65 + el]        = hr[lane + 32 * u];
            Abuf[(128 + lane + 32 * u) * 65 + el]  = hc[lane + 32 * u];
        }
        if (lane < 16)
            Abuf[(256 + lane) * 65 + el] = edge_attr[(size_t)e * 16 + lane];
    }
    __syncthreads();

    // ---- 9 fused layers ---------------------------------------------------
    const int trow = wid;   // 0..7
    const int tcol = lane;  // 0..31

    for (int layer = 0; layer < 9; ++layer) {
        float* In  = (layer & 1) ? Cbuf : Abuf;
        float* Out = (layer & 1) ? Abuf : Cbuf;
        const float* Wl; const float* bl; int K;
        if (layer == 0) { Wl = W0; bl = b0; K = D_EDGE; }
        else {
            Wl = Wmid + (size_t)(layer - 1) * HID * HID;
            bl = bmid + (size_t)(layer - 1) * HID;
            K  = HID;
        }

        float c[8][8];
        #pragma unroll
        for (int i = 0; i < 8; ++i)
            #pragma unroll
            for (int j = 0; j < 8; ++j) c[i][j] = 0.f;

        const int nkt = K / 16;     // 17 for layer 0, 16 otherwise
        for (int kt = 0; kt < nkt; ++kt) {
            // load W tile [16][256] = 1024 float4, 4 per thread
            #pragma unroll
            for (int r = 0; r < 4; ++r) {
                int p  = tid + r * 256;
                int k  = p >> 6;          // 64 float4 per row
                int n4 = p & 63;
                *(float4*)&Ws[k * 256 + n4 * 4] =
                    *(const float4*)(Wl + (size_t)(kt * 16 + k) * HID + n4 * 4);
            }
            __syncthreads();
            #pragma unroll
            for (int k = 0; k < 16; ++k) {
                float a[8], b[8];
                const float* Ain = In + (kt * 16 + k) * 65 + trow * 8;
                #pragma unroll
                for (int i = 0; i < 8; ++i) a[i] = Ain[i];
                #pragma unroll
                for (int j = 0; j < 8; ++j) b[j] = Ws[k * 256 + tcol + 32 * j];
                #pragma unroll
                for (int i = 0; i < 8; ++i)
                    #pragma unroll
                    for (int j = 0; j < 8; ++j) c[i][j] += a[i] * b[j];
            }
            __syncthreads();
        }

        // epilogue: bias + leaky, store transposed into Out[n][m]
        #pragma unroll
        for (int j = 0; j < 8; ++j) {
            float bb = bl[tcol + 32 * j];
            #pragma unroll
            for (int i = 0; i < 8; ++i) {
                float v = c[i][j] + bb;
                v = (v >= 0.f) ? v : NEG * v;
                Out[(tcol + 32 * j) * 65 + trow * 8 + i] = v;
            }
        }
        // no sync needed: next iteration's Ws load writes a disjoint region,
        // and the sync inside the kt loop orders epilogue-writes vs reads.
    }
    // final activations are in Cbuf (layer 8 wrote Out = Cbuf)

    // ---- classifier: logits = h @ Wlast + blast ---------------------------
    for (int r = tid; r < HID * 3; r += 256) Ws[r] = Wlast[r];
    __syncthreads();   // also orders layer-8 epilogue vs Cbuf reads below

    if (tid < 64 * 3) {
        const int m = tid / 3, n = tid % 3;
        float acc = blast[n];
        #pragma unroll 8
        for (int k = 0; k < HID; ++k)
            acc += Cbuf[k * 65 + m] * Ws[k * 3 + n];
        Lg[m * 4 + n] = acc;
    }
    __syncthreads();

    // ---- log_softmax over 3 classes ---------------------------------------
    if (tid < 64) {
        float l0 = Lg[tid * 4 + 0];
        float l1 = Lg[tid * 4 + 1];
        float l2 = Lg[tid * 4 + 2];
        float mx = fmaxf(l0, fmaxf(l1, l2));
        float s  = expf(l0 - mx) + expf(l1 - mx) + expf(l2 - mx);
        float lse = mx + logf(s);
        size_t o = (size_t)(e0 + tid) * 3;
        out[o + 0] = l0 - lse;
        out[o + 1] = l1 - lse;
        out[o + 2] = l2 - lse;
    }
}

// ---------------------------------------------------------------------------
extern "C" void kernel_launch(void* const* d_in, const int* in_sizes, int n_in,
                              void* d_out, int out_size)
{
    const float* x   = (const float*)d_in[0];
    const void*  ei  = d_in[1];
    const float* ea  = (const float*)d_in[2];
    const float* Wx  = (const float*)d_in[3];
    const float* bx  = (const float*)d_in[4];
    const float* W0  = (const float*)d_in[5];
    const float* b0  = (const float*)d_in[6];
    const float* Wm  = (const float*)d_in[7];
    const float* bm  = (const float*)d_in[8];
    const float* Wl  = (const float*)d_in[9];
    const float* bl  = (const float*)d_in[10];
    float* out = (float*)d_out;

    (void)in_sizes; (void)n_in; (void)out_size;

    cudaFuncSetAttribute(edge_mlp_kernel,
                         cudaFuncAttributeMaxDynamicSharedMemorySize, SMEM_BYTES);

    detect_idx_kernel<<<1, 1>>>((const int*)ei);
    node_mlp_kernel<<<N_NODES / 64, 256>>>(x, Wx, bx);
    edge_mlp_kernel<<<E_EDGES / 64, 256, SMEM_BYTES>>>(
        ei, ea, W0, b0, Wm, bm, Wl, bl, out);
}

// round 6
// speedup vs baseline: 1.0006x; 1.0006x over previous
#include <cuda_runtime.h>
#include <math.h>

// ---------------------------------------------------------------------------
// EdgeClassNet fused implementation (Round 0: fp32 FFMA baseline)
//
//   h_node = leaky(x @ Wx + bx)                       [65536,128]  (kernel 1)
//   ef     = concat(h[row], h[col], edge_attr)        [E,272]      (fused)
//   h      = leaky(ef @ W0 + b0); 8x leaky(h@Wm+bm)   [E,256]      (fused)
//   out    = log_softmax(h @ Wlast + blast)           [E,3]        (fused)
//
// Kernel 2 keeps the per-64-edge activation tile resident in SMEM across all
// 9 layers (ping-pong buffers), so only weights stream from L2.
// ---------------------------------------------------------------------------

#define N_NODES 65536
#define E_EDGES 262144
#define D_NODE  256
#define D_HN    128       // node-MLP output dim
#define D_EDGE  272       // 128 + 128 + 16
#define HID     256
#define NEG     0.01f

// scratch: node features after node MLP (32 MB, fits easily in L2 once warm)
__device__ float g_h[(size_t)N_NODES * D_HN];
__device__ int   g_idx64;   // 1 if edge_index is int64, 0 if int32

// ---------------------------------------------------------------------------
// Detect int32 vs int64 edge_index layout at runtime (device-side, capturable).
// int64 little-endian with values in [0,65536) => every odd 32-bit word is 0.
// ---------------------------------------------------------------------------
__global__ void detect_idx_kernel(const int* __restrict__ ei32) {
    int all0 = 1;
    #pragma unroll 1
    for (int i = 0; i < 64; ++i) {
        if (ei32[2 * i + 1] != 0) { all0 = 0; break; }
    }
    g_idx64 = all0;
}

// ---------------------------------------------------------------------------
// Kernel 1: node MLP.  h_node = leaky(x @ Wx + bx),  M=65536 K=256 N=128.
// CTA: 64 rows x 128 cols, 256 threads, 8x4 register microtile per thread.
// ---------------------------------------------------------------------------
__global__ __launch_bounds__(256, 1) void node_mlp_kernel(
    const float* __restrict__ x, const float* __restrict__ Wx,
    const float* __restrict__ bx)
{
    __shared__ float Xs[16][65];    // [k][m], padded
    __shared__ float Ws[16][128];   // [k][n]

    const int tid  = threadIdx.x;
    const int row0 = blockIdx.x * 64;
    const int trow = tid >> 5;      // 0..7  (warp id)
    const int tcol = tid & 31;      // lane

    float c[8][4];
    #pragma unroll
    for (int i = 0; i < 8; ++i)
        #pragma unroll
        for (int j = 0; j < 4; ++j) c[i][j] = 0.f;

    const int lm = tid >> 2;          // 0..63 : row within tile
    const int lk = (tid & 3) * 4;     // 0,4,8,12 : k offset

    for (int kt = 0; kt < D_NODE; kt += 16) {
        // load X tile (transposed into Xs[k][m])
        float4 xv = *(const float4*)(x + (size_t)(row0 + lm) * D_NODE + kt + lk);
        Xs[lk + 0][lm] = xv.x;
        Xs[lk + 1][lm] = xv.y;
        Xs[lk + 2][lm] = xv.z;
        Xs[lk + 3][lm] = xv.w;
        // load W tile [16][128] = 512 float4, 2 per thread
        #pragma unroll
        for (int r = 0; r < 2; ++r) {
            int p  = tid + r * 256;     // float4 index
            int k  = p >> 5;            // 32 float4 per row
            int n4 = p & 31;
            *(float4*)&Ws[k][n4 * 4] =
                *(const float4*)(Wx + (size_t)(kt + k) * D_HN + n4 * 4);
        }
        __syncthreads();
        #pragma unroll
        for (int k = 0; k < 16; ++k) {
            float a[8], b[4];
            #pragma unroll
            for (int i = 0; i < 8; ++i) a[i] = Xs[k][trow * 8 + i];
            #pragma unroll
            for (int j = 0; j < 4; ++j) b[j] = Ws[k][tcol + 32 * j];
            #pragma unroll
            for (int i = 0; i < 8; ++i)
                #pragma unroll
                for (int j = 0; j < 4; ++j) c[i][j] += a[i] * b[j];
        }
        __syncthreads();
    }

    #pragma unroll
    for (int j = 0; j < 4; ++j) {
        float bb = bx[tcol + 32 * j];
        #pragma unroll
        for (int i = 0; i < 8; ++i) {
            float v = c[i][j] + bb;
            v = (v >= 0.f) ? v : NEG * v;
            g_h[(size_t)(row0 + trow * 8 + i) * D_HN + tcol + 32 * j] = v;
        }
    }
}

// ---------------------------------------------------------------------------
// Kernel 2: fused edge pipeline. One CTA = 64 edges, activations resident in
// SMEM across all layers. 256 threads, 8x8 register microtile per thread.
//
// Dynamic SMEM layout (floats):
//   Abuf [272][65]   at 0        (17680)
//   Cbuf [256][65]   at 17680    (16640)
//   Ws   [16][256]   at 34320    ( 4096)   (also reused for Wlast: 768 floats)
//   Lg   [64][4]     at 38416    (  256)
// total 38672 floats = 154688 bytes
// ---------------------------------------------------------------------------
#define SMEM_FLOATS 38672
#define SMEM_BYTES  (SMEM_FLOATS * 4)

__global__ __launch_bounds__(256, 1) void edge_mlp_kernel(
    const void*  __restrict__ edge_index,
    const float* __restrict__ edge_attr,
    const float* __restrict__ W0,    const float* __restrict__ b0,
    const float* __restrict__ Wmid,  const float* __restrict__ bmid,
    const float* __restrict__ Wlast, const float* __restrict__ blast,
    float* __restrict__ out)
{
    extern __shared__ float smf[];
    float* Abuf = smf;                    // pitch 65, 272 rows
    float* Cbuf = smf + 272 * 65;         // pitch 65, 256 rows
    float* Ws   = Cbuf + 256 * 65;        // [16][256]
    float* Lg   = Ws + 16 * 256;          // [64][4]

    const int tid  = threadIdx.x;
    const int wid  = tid >> 5;
    const int lane = tid & 31;
    const int e0   = blockIdx.x * 64;

    const bool is64 = (g_idx64 != 0);
    const int*       ei32 = (const int*)edge_index;
    const long long* ei64 = (const long long*)edge_index;

    // ---- gather: ef[k][m] = concat(h[row], h[col], edge_attr) -------------
    // warp w handles local edges w*8 .. w*8+7
    for (int el = wid * 8; el < wid * 8 + 8; ++el) {
        const int e = e0 + el;
        const int r  = is64 ? (int)ei64[e]           : ei32[e];
        const int cc = is64 ? (int)ei64[E_EDGES + e] : ei32[E_EDGES + e];
        const float* hr = g_h + (size_t)r  * D_HN;
        const float* hc = g_h + (size_t)cc * D_HN;
        #pragma unroll
        for (int u = 0; u < 4; ++u) {
            Abuf[(lane + 32 * u) * 65 + el]        = hr[lane + 32 * u];
            Abuf[(128 + lane + 32 * u) * 65 + el]  = hc[lane + 32 * u];
        }
        if (lane < 16)
            Abuf[(256 + lane) * 65 + el] = edge_attr[(size_t)e * 16 + lane];
    }
    __syncthreads();

    // ---- 9 fused layers ---------------------------------------------------
    const int trow = wid;   // 0..7
    const int tcol = lane;  // 0..31

    for (int layer = 0; layer < 9; ++layer) {
        float* In  = (layer & 1) ? Cbuf : Abuf;
        float* Out = (layer & 1) ? Abuf : Cbuf;
        const float* Wl; const float* bl; int K;
        if (layer == 0) { Wl = W0; bl = b0; K = D_EDGE; }
        else {
            Wl = Wmid + (size_t)(layer - 1) * HID * HID;
            bl = bmid + (size_t)(layer - 1) * HID;
            K  = HID;
        }

        float c[8][8];
        #pragma unroll
        for (int i = 0; i < 8; ++i)
            #pragma unroll
            for (int j = 0; j < 8; ++j) c[i][j] = 0.f;

        const int nkt = K / 16;     // 17 for layer 0, 16 otherwise
        for (int kt = 0; kt < nkt; ++kt) {
            // load W tile [16][256] = 1024 float4, 4 per thread
            #pragma unroll
            for (int r = 0; r < 4; ++r) {
                int p  = tid + r * 256;
                int k  = p >> 6;          // 64 float4 per row
                int n4 = p & 63;
                *(float4*)&Ws[k * 256 + n4 * 4] =
                    *(const float4*)(Wl + (size_t)(kt * 16 + k) * HID + n4 * 4);
            }
            __syncthreads();
            #pragma unroll
            for (int k = 0; k < 16; ++k) {
                float a[8], b[8];
                const float* Ain = In + (kt * 16 + k) * 65 + trow * 8;
                #pragma unroll
                for (int i = 0; i < 8; ++i) a[i] = Ain[i];
                #pragma unroll
                for (int j = 0; j < 8; ++j) b[j] = Ws[k * 256 + tcol + 32 * j];
                #pragma unroll
                for (int i = 0; i < 8; ++i)
                    #pragma unroll
                    for (int j = 0; j < 8; ++j) c[i][j] += a[i] * b[j];
            }
            __syncthreads();
        }

        // epilogue: bias + leaky, store transposed into Out[n][m]
        #pragma unroll
        for (int j = 0; j < 8; ++j) {
            float bb = bl[tcol + 32 * j];
            #pragma unroll
            for (int i = 0; i < 8; ++i) {
                float v = c[i][j] + bb;
                v = (v >= 0.f) ? v : NEG * v;
                Out[(tcol + 32 * j) * 65 + trow * 8 + i] = v;
            }
        }
        // no sync needed: next iteration's Ws load writes a disjoint region,
        // and the sync inside the kt loop orders epilogue-writes vs reads.
    }
    // final activations are in Cbuf (layer 8 wrote Out = Cbuf)

    // ---- classifier: logits = h @ Wlast + blast ---------------------------
    for (int r = tid; r < HID * 3; r += 256) Ws[r] = Wlast[r];
    __syncthreads();   // also orders layer-8 epilogue vs Cbuf reads below

    if (tid < 64 * 3) {
        const int m = tid / 3, n = tid % 3;
        float acc = blast[n];
        #pragma unroll 8
        for (int k = 0; k < HID; ++k)
            acc += Cbuf[k * 65 + m] * Ws[k * 3 + n];
        Lg[m * 4 + n] = acc;
    }
    __syncthreads();

    // ---- log_softmax over 3 classes ---------------------------------------
    if (tid < 64) {
        float l0 = Lg[tid * 4 + 0];
        float l1 = Lg[tid * 4 + 1];
        float l2 = Lg[tid * 4 + 2];
        float mx = fmaxf(l0, fmaxf(l1, l2));
        float s  = expf(l0 - mx) + expf(l1 - mx) + expf(l2 - mx);
        float lse = mx + logf(s);
        size_t o = (size_t)(e0 + tid) * 3;
        out[o + 0] = l0 - lse;
        out[o + 1] = l1 - lse;
        out[o + 2] = l2 - lse;
    }
}

// ---------------------------------------------------------------------------
extern "C" void kernel_launch(void* const* d_in, const int* in_sizes, int n_in,
                              void* d_out, int out_size)
{
    const float* x   = (const float*)d_in[0];
    const void*  ei  = d_in[1];
    const float* ea  = (const float*)d_in[2];
    const float* Wx  = (const float*)d_in[3];
    const float* bx  = (const float*)d_in[4];
    const float* W0  = (const float*)d_in[5];
    const float* b0  = (const float*)d_in[6];
    const float* Wm  = (const float*)d_in[7];
    const float* bm  = (const float*)d_in[8];
    const float* Wl  = (const float*)d_in[9];
    const float* bl  = (const float*)d_in[10];
    float* out = (float*)d_out;

    (void)in_sizes; (void)n_in; (void)out_size;

    cudaFuncSetAttribute(edge_mlp_kernel,
                         cudaFuncAttributeMaxDynamicSharedMemorySize, SMEM_BYTES);

    detect_idx_kernel<<<1, 1>>>((const int*)ei);
    node_mlp_kernel<<<N_NODES / 64, 256>>>(x, Wx, bx);
    edge_mlp_kernel<<<E_EDGES / 64, 256, SMEM_BYTES>>>(
        ei, ea, W0, b0, Wm, bm, Wl, bl, out);
}